// round 7
// baseline (speedup 1.0000x reference)
#include <cuda_runtime.h>

// Problem constants (fixed by the dataset)
#define B_    64
#define OBJS_ 2048
#define D_    256
#define K_    2
#define N_    (B_*OBJS_)          // 131072
#define BDK   (B_*D_*K_)          // 32768
#define NK    (N_*K_)             // 262144

#define PROD  128                 // producer CTAs (16-row slab of every scene each)
#define NCTA  296                 // 2 CTAs/SM * 148 SMs — fully co-resident
#define ROWS_PER_PROD (OBJS_/PROD)   // 16
#define CC    8                   // consumer chunks per scene
#define CHUNK_ROWS (OBJS_/CC)     // 256
#define NTASK (B_*CC)             // 512 tickets
#define THREADS 256
#define NWARP 8
#define ROWS_PER_WARP (CHUNK_ROWS/NWARP) // 32

typedef unsigned long long u64;

// Scratch (device globals — allocation-free rule)
__device__ float g_ctxsum[B_*D_];        // per-scene column sums (atomic accum)
__device__ float g_featp[NTASK*D_*K_];   // per-task pooled-feature partials
__device__ float g_zsump[NTASK*K_];      // per-task softmax-denominator partials
__device__ float g_z[NK];                // per-object unnormalized numerators
__device__ int   g_ready[B_];            // per-scene producer arrival counts
__device__ int   g_done[B_];             // per-scene consumed-chunk counts
__device__ int   g_ticket;               // consume queue head
__device__ int   g_pbar;                 // producer start barrier (after zeroing)
__device__ int   g_ack;                  // end-of-kernel ack for reset

// ---- packed f32x2 helpers --------------------------------------------------
__device__ __forceinline__ u64 pack2(float lo, float hi) {
    u64 r; asm("mov.b64 %0,{%1,%2};" : "=l"(r) : "f"(lo), "f"(hi)); return r;
}
__device__ __forceinline__ float2 unpack2(u64 v) {
    float lo, hi; asm("mov.b64 {%0,%1},%2;" : "=f"(lo), "=f"(hi) : "l"(v));
    return make_float2(lo, hi);
}
__device__ __forceinline__ u64 add2(u64 a, u64 b) {
    u64 d; asm("add.rn.f32x2 %0,%1,%2;" : "=l"(d) : "l"(a), "l"(b)); return d;
}
__device__ __forceinline__ u64 fma2(u64 a, u64 b, u64 c) {
    u64 d; asm("fma.rn.f32x2 %0,%1,%2,%3;" : "=l"(d) : "l"(a), "l"(b), "l"(c)); return d;
}
__device__ __forceinline__ u64 abs2(u64 a) {   // clear both sign bits (ALU pipe)
    u64 d; asm("and.b64 %0,%1,0x7FFFFFFF7FFFFFFF;" : "=l"(d) : "l"(a)); return d;
}

// ---------------------------------------------------------------------------
__global__ __launch_bounds__(THREADS, 2) void fusedK(
    const float* __restrict__ x,
    const float* __restrict__ att,
    const float* __restrict__ scale,
    const float* __restrict__ cb,
    const int*   __restrict__ num_objs,
    float*       __restrict__ out,
    int out_size)
{
    __shared__ __align__(16) float sctx[D_];           // scene mean context
    __shared__ float sfeat[D_*K_];                     // feature accum (2 KB)
    __shared__ __align__(8) float sz[CHUNK_ROWS*K_];   // per-row z (2 KB)
    __shared__ float sbt[K_];
    __shared__ float szs[K_];
    __shared__ int   st, slast;

    const int cta  = blockIdx.x;
    const int tid  = threadIdx.x;
    const int warp = tid >> 5, lane = tid & 31;

    // =================== PRODUCER PHASE (CTAs 0..127) ======================
    if (cta < PROD) {
        // zero my 1/128 slice of the scene-sum accumulator
        if (tid < 128) g_ctxsum[cta*128 + tid] = 0.f;
        __threadfence();
        __syncthreads();
        if (tid == 0) {                 // producers-only start barrier
            atomicAdd(&g_pbar, 1);
            volatile int* p = &g_pbar;
            while (*p < PROD) __nanosleep(64);
        }
        __syncthreads();

        // stream scenes IN ORDER; this CTA owns rows [cta*16, cta*16+16) of
        // every scene; thread = one column. Two scenes per step for MLP.
        const float* xc = x + (size_t)cta*ROWS_PER_PROD*D_ + tid;
        for (int b = 0; b < B_; b += 2) {
            const float* p0 = xc + (size_t)b    *OBJS_*D_;
            const float* p1 = xc + (size_t)(b+1)*OBJS_*D_;
            float a0 = 0.f, a1 = 0.f;
            #pragma unroll
            for (int r = 0; r < ROWS_PER_PROD; r++) {
                a0 += p0[(size_t)r*D_];
                a1 += p1[(size_t)r*D_];
            }
            atomicAdd(&g_ctxsum[ b   *D_ + tid], a0);
            atomicAdd(&g_ctxsum[(b+1)*D_ + tid], a1);
            __threadfence();
            __syncthreads();
            if (tid == 0) {
                atomicAdd(&g_ready[b],   1);
                atomicAdd(&g_ready[b+1], 1);
            }
        }
    }

    // =================== CONSUMER SETUP (all CTAs) =========================
    // bias_term = channel_bias @ att_shared
    if (tid < 64) {
        int k = tid >> 5, l = tid & 31;
        float s = 0.f;
        #pragma unroll
        for (int j = 0; j < 8; j++) s += cb[k*D_ + l + 32*j] * att[l + 32*j];
        #pragma unroll
        for (int m = 16; m; m >>= 1) s += __shfl_xor_sync(0xffffffffu, s, m);
        if (l == 0) sbt[k] = s;
    }
    __syncthreads();

    // per-lane invariant att_shared factors:
    // lrelu(t) = 0.6t + 0.4|t|  ->  a*lrelu = (0.6a)*t + (0.4a)*|t|
    float4 a_a = ((const float4*)att)[lane];
    float4 a_b = ((const float4*)att)[lane + 32];
    const u64 a6_0 = pack2(0.6f*a_a.x, 0.6f*a_a.y), a6_1 = pack2(0.6f*a_a.z, 0.6f*a_a.w);
    const u64 a6_2 = pack2(0.6f*a_b.x, 0.6f*a_b.y), a6_3 = pack2(0.6f*a_b.z, 0.6f*a_b.w);
    const u64 a4_0 = pack2(0.4f*a_a.x, 0.4f*a_a.y), a4_1 = pack2(0.4f*a_a.z, 0.4f*a_a.w);
    const u64 a4_2 = pack2(0.4f*a_b.x, 0.4f*a_b.y), a4_3 = pack2(0.4f*a_b.z, 0.4f*a_b.w);

    const float bt0 = sbt[0], bt1 = sbt[1];
    const float s0  = scale[0], s1 = scale[1];
    const bool full_out = (out_size >= BDK + NK);
    const bool attn_any = full_out || (out_size == NK);

    // =================== CONSUME QUEUE (all CTAs) ==========================
    while (true) {
        if (tid == 0) st = atomicAdd(&g_ticket, 1);
        __syncthreads();
        const int t = st;
        if (t >= NTASK) break;
        const int b = t >> 3, chunk = t & 7;

        if (tid == 0) {                       // wait for scene to be produced
            volatile int* f = &g_ready[b];
            while (*f < PROD) __nanosleep(128);
        }
        __syncthreads();
        __threadfence();

        const float invc = 1.f / fmaxf((float)num_objs[b], 1.f);
        sctx[tid] = g_ctxsum[b*D_ + tid] * invc;
        for (int i = tid; i < D_*K_; i += THREADS) sfeat[i] = 0.f;
        if (tid < K_) szs[tid] = 0.f;
        __syncthreads();

        // --- fused logits + exp + weighted pooling on 256 rows ------------
        float4 cxa = ((const float4*)sctx)[lane];
        float4 cxb = ((const float4*)sctx)[lane + 32];
        u64 c0 = pack2(cxa.x, cxa.y), c1 = pack2(cxa.z, cxa.w);
        u64 c2 = pack2(cxb.x, cxb.y), c3 = pack2(cxb.z, cxb.w);

        u64 f0_0=0,f0_1=0,f0_2=0,f0_3=0;   // k=0 pooled features (packed)
        u64 f1_0=0,f1_1=0,f1_2=0,f1_3=0;   // k=1
        float zs0 = 0.f, zs1 = 0.f;

        const int rowbase = b*OBJS_ + chunk*CHUNK_ROWS + warp*ROWS_PER_WARP;

        #pragma unroll 4
        for (int r = 0; r < ROWS_PER_WARP; r++) {
            int row = rowbase + r;
            const ulonglong2* xr = (const ulonglong2*)(x + (size_t)row * D_);
            ulonglong2 xa = xr[lane];
            ulonglong2 xb = xr[lane + 32];

            u64 t0 = add2(xa.x, c0), t1 = add2(xa.y, c1);
            u64 t2 = add2(xb.x, c2), t3 = add2(xb.y, c3);

            u64 accA = fma2(a6_0, t0, fma2(a4_0, abs2(t0), 0ull));
            accA     = fma2(a6_1, t1, fma2(a4_1, abs2(t1), accA));
            u64 accB = fma2(a6_2, t2, fma2(a4_2, abs2(t2), 0ull));
            accB     = fma2(a6_3, t3, fma2(a4_3, abs2(t3), accB));
            float2 p = unpack2(add2(accA, accB));
            float acc = p.x + p.y;
            #pragma unroll
            for (int m = 16; m; m >>= 1)
                acc += __shfl_xor_sync(0xffffffffu, acc, m);

            float z0 = __expf((acc + bt0) * s0);
            float z1 = __expf((acc + bt1) * s1);
            zs0 += z0; zs1 += z1;
            if (lane == 0)
                *(float2*)&sz[(warp*ROWS_PER_WARP + r)*2] = make_float2(z0, z1);

            u64 zz0 = pack2(z0, z0), zz1 = pack2(z1, z1);
            f0_0 = fma2(xa.x, zz0, f0_0); f0_1 = fma2(xa.y, zz0, f0_1);
            f0_2 = fma2(xb.x, zz0, f0_2); f0_3 = fma2(xb.y, zz0, f0_3);
            f1_0 = fma2(xa.x, zz1, f1_0); f1_1 = fma2(xa.y, zz1, f1_1);
            f1_2 = fma2(xb.x, zz1, f1_2); f1_3 = fma2(xb.y, zz1, f1_3);
        }

        // cross-warp combine (lanes hit distinct smem addrs within a warp)
        {
            int d0 = 4*lane, d1 = 128 + 4*lane;
            float2 v;
            v = unpack2(f0_0); atomicAdd(&sfeat[(d0+0)*2+0], v.x); atomicAdd(&sfeat[(d0+1)*2+0], v.y);
            v = unpack2(f0_1); atomicAdd(&sfeat[(d0+2)*2+0], v.x); atomicAdd(&sfeat[(d0+3)*2+0], v.y);
            v = unpack2(f0_2); atomicAdd(&sfeat[(d1+0)*2+0], v.x); atomicAdd(&sfeat[(d1+1)*2+0], v.y);
            v = unpack2(f0_3); atomicAdd(&sfeat[(d1+2)*2+0], v.x); atomicAdd(&sfeat[(d1+3)*2+0], v.y);
            v = unpack2(f1_0); atomicAdd(&sfeat[(d0+0)*2+1], v.x); atomicAdd(&sfeat[(d0+1)*2+1], v.y);
            v = unpack2(f1_1); atomicAdd(&sfeat[(d0+2)*2+1], v.x); atomicAdd(&sfeat[(d0+3)*2+1], v.y);
            v = unpack2(f1_2); atomicAdd(&sfeat[(d1+0)*2+1], v.x); atomicAdd(&sfeat[(d1+1)*2+1], v.y);
            v = unpack2(f1_3); atomicAdd(&sfeat[(d1+2)*2+1], v.x); atomicAdd(&sfeat[(d1+3)*2+1], v.y);
        }
        if (lane == 0) { atomicAdd(&szs[0], zs0); atomicAdd(&szs[1], zs1); }
        __syncthreads();

        // publish task partials (plain stores)
        for (int i = tid; i < D_*K_; i += THREADS)
            g_featp[(size_t)t*(D_*K_) + i] = sfeat[i];
        {
            const float2* z2 = (const float2*)sz;
            float2* gz2 = ((float2*)g_z) + b*OBJS_ + chunk*CHUNK_ROWS;
            for (int i = tid; i < CHUNK_ROWS; i += THREADS) gz2[i] = z2[i];
        }
        if (tid < K_) g_zsump[t*K_ + tid] = szs[tid];

        __threadfence();
        __syncthreads();
        if (tid == 0) {
            int old = atomicAdd(&g_done[b], 1);
            slast = (old == CC-1);
        }
        __syncthreads();

        // ---- last chunk of the scene: finalize features + attention ------
        if (slast) {
            __threadfence();
            float zt0 = 0.f, zt1 = 0.f;
            #pragma unroll
            for (int j = 0; j < CC; j++) {
                zt0 += g_zsump[(b*CC + j)*K_ + 0];
                zt1 += g_zsump[(b*CC + j)*K_ + 1];
            }
            float inv0 = 1.f/zt0, inv1 = 1.f/zt1;
            if (out_size >= BDK) {
                float2 f = {0.f, 0.f};
                #pragma unroll
                for (int j = 0; j < CC; j++) {
                    float2 v = ((const float2*)&g_featp[(size_t)(b*CC + j)*(D_*K_)])[tid];
                    f.x += v.x; f.y += v.y;
                }
                ((float2*)out)[b*D_ + tid] = make_float2(f.x*inv0, f.y*inv1);
            }
            if (attn_any) {
                int obase = full_out ? (BDK/2) : 0;
                const float2* gz2 = ((const float2*)g_z) + b*OBJS_;
                float2* o2 = ((float2*)out) + obase + b*OBJS_;
                for (int i = tid; i < OBJS_; i += THREADS) {
                    float2 z = gz2[i];
                    o2[i] = make_float2(z.x*inv0, z.y*inv1);
                }
            }
        }
        __syncthreads();
    }

    // =================== RESET (last CTA to finish) ========================
    if (tid == 0) {
        int a = atomicAdd(&g_ack, 1);
        if (a == NCTA-1) {
            for (int i = 0; i < B_; i++) { g_ready[i] = 0; g_done[i] = 0; }
            g_ticket = 0; g_pbar = 0; g_ack = 0;
        }
    }
}

// ---------------------------------------------------------------------------
extern "C" void kernel_launch(void* const* d_in, const int* in_sizes, int n_in,
                              void* d_out, int out_size)
{
    const float* x        = (const float*)d_in[0];  // [N, D]
    const int*   num_objs = (const int*)  d_in[1];  // [B]
    const float* att      = (const float*)d_in[2];  // [1, D]
    const float* scale    = (const float*)d_in[3];  // [K, 1]
    const float* cb       = (const float*)d_in[4];  // [K, D]
    float*       out      = (float*)d_out;

    fusedK<<<NCTA, THREADS>>>(x, att, scale, cb, num_objs, out, out_size);
}